// round 8
// baseline (speedup 1.0000x reference)
#include <cuda_runtime.h>
#include <cuda_bf16.h>
#include <stdint.h>

#define B_ 64
#define F_ 4
#define V_ 256
#define D_ 16384
#define ITERS_ 10
#define KCH 32               // split-K chunks for stage 2
#define KC (D_/KCH)          // 512 k per chunk
#define NB 128               // persistent grid size (all co-resident: 128 < 148 SMs)

// ---------------- static device scratch (no runtime allocation) ----------------
__device__ __align__(16) __nv_bfloat16 g_in_bf [B_*D_];
__device__ __align__(16) __nv_bfloat16 g_est_bf[B_*F_*D_];
__device__ __align__(16) __nv_bfloat16 g_T_bf  [B_*D_];
__device__ __align__(16) __nv_bfloat16 g_cbK   [(size_t)F_*V_*D_];
__device__ __align__(16) __nv_bfloat16 g_cbD   [(size_t)F_*D_*V_];
__device__ __align__(16) float         g_simp  [(size_t)KCH*F_*B_*V_];
__device__ __align__(16) float         g_sim   [F_*B_*V_];
__device__ __align__(16) __nv_bfloat16 g_Ah    [F_*B_*V_];
__device__ __align__(16) __nv_bfloat16 g_Al    [F_*B_*V_];

// ---------------- software grid barrier (sense-reversing; state self-restoring) --------
__device__ int          g_count = 0;
__device__ volatile int g_sense = 0;

__device__ __forceinline__ void gbar(int& lsense) {
    __syncthreads();
    if (threadIdx.x == 0) {
        lsense ^= 1;
        __threadfence();
        if (atomicAdd(&g_count, 1) == NB - 1) {
            atomicExch(&g_count, 0);       // reset for next barrier
            __threadfence();
            g_sense = lsense;              // release
        } else {
            while (g_sense != lsense) { }  // spin (volatile load -> L2)
        }
    }
    __syncthreads();
    __threadfence();                       // sm_103a: gpu-scope fence flushes L1D
}

// ---------------- mma.sync helper (bf16, fp32 accum — exact for our integer data) ----
__device__ __forceinline__ void mma16816(float c[4], const uint32_t a[4], const uint32_t b[2]) {
    asm volatile(
        "mma.sync.aligned.m16n8k16.row.col.f32.bf16.bf16.f32 "
        "{%0,%1,%2,%3},{%4,%5,%6,%7},{%8,%9},{%0,%1,%2,%3};\n"
        : "+f"(c[0]), "+f"(c[1]), "+f"(c[2]), "+f"(c[3])
        : "r"(a[0]), "r"(a[1]), "r"(a[2]), "r"(a[3]), "r"(b[0]), "r"(b[1]));
}

__device__ __forceinline__ void ldsm_x4(uint32_t& r0, uint32_t& r1, uint32_t& r2, uint32_t& r3,
                                        uint32_t saddr) {
    asm volatile("ldmatrix.sync.aligned.m8n8.x4.shared.b16 {%0,%1,%2,%3}, [%4];"
                 : "=r"(r0), "=r"(r1), "=r"(r2), "=r"(r3) : "r"(saddr));
}

// ---------------- conversion kernels ----------------
__global__ void k_sign_pairs(const float* __restrict__ src, int which, int npairs) {
    int i = blockIdx.x * blockDim.x + threadIdx.x;
    if (i >= npairs) return;
    uint2 u = ((const uint2*)src)[i];
    uint32_t w = 0x3F803F80u | ((u.x >> 16) & 0x8000u) | (u.y & 0x80000000u);
    uint32_t* dst = (which == 0) ? (uint32_t*)g_in_bf
                  : (which == 1) ? (uint32_t*)g_est_bf
                                 : (uint32_t*)g_cbK;
    dst[i] = w;
}

__global__ void k_trans(const float* __restrict__ cb) {
    __shared__ unsigned short ts[32][33];
    int f = blockIdx.z, d0 = blockIdx.x * 32, v0 = blockIdx.y * 32;
    int tx = threadIdx.x & 31, ty = threadIdx.x >> 5;  // 32 x 8
#pragma unroll
    for (int r = 0; r < 4; r++) {
        int v = v0 + ty + r * 8;
        uint32_t ub = __float_as_uint(cb[((size_t)(f * V_ + v)) * D_ + d0 + tx]);
        ts[ty + r * 8][tx] = (unsigned short)(0x3F80u | ((ub >> 16) & 0x8000u));
    }
    __syncthreads();
#pragma unroll
    for (int r = 0; r < 4; r++) {
        int d = d0 + ty + r * 8;
        ((unsigned short*)g_cbD)[((size_t)(f * D_ + d)) * V_ + v0 + tx] = ts[tx][ty + r * 8];
    }
}

// ================= persistent-kernel phase bodies =================

// T = input * prod_f est (bf16 sign XOR); 4 uint4 per thread
__device__ __forceinline__ void phase_total(int bid) {
    const int tid0 = bid * 256 + threadIdx.x;
#pragma unroll
    for (int q = 0; q < 4; q++) {
        int i = tid0 + q * (NB * 256);               // uint4 index over B_*D_ elems /8
        int e0 = i * 8;
        int b = e0 / D_, d = e0 % D_;
        uint4 t = *(const uint4*)(g_in_bf + (size_t)b * D_ + d);
#pragma unroll
        for (int ff = 0; ff < F_; ff++) {
            uint4 e = __ldcg((const uint4*)(g_est_bf + ((size_t)b * F_ + ff) * D_ + d));
            t.x ^= e.x; t.y ^= e.y; t.z ^= e.z; t.w ^= e.w;
        }
        *(uint4*)(g_T_bf + (size_t)b * D_ + d) = t;
    }
}

// stage 2: sim partials for (kc, f) = (bid>>2, bid&3)
__device__ __forceinline__ void phase_sim(uint8_t* sm, int bid, int mode) {
    __nv_bfloat16* As = (__nv_bfloat16*)sm;                 // 64 x 72  (9216 B)
    __nv_bfloat16* Bs = (__nv_bfloat16*)(sm + 9216);        // 256 x 72 (36864 B)
    const int kc = bid >> 2, f = bid & 3;
    const int tid = threadIdx.x;
    const int w = tid >> 5, lane = tid & 31, g = lane >> 2, t = lane & 3;
    const int arow = tid >> 2, aseg = tid & 3;
    const int vB = tid >> 3, chB = tid & 7;

    const uint4* pe = (const uint4*)(g_est_bf + ((size_t)arow * F_ + f) * D_);
    const uint4* pt = (const uint4*)(g_T_bf + (size_t)arow * D_);

    const uint32_t asBase = (uint32_t)__cvta_generic_to_shared(As);
    const uint32_t bsBase = (uint32_t)__cvta_generic_to_shared(Bs);
    const int laneRow  = lane & 15;
    const int laneColH = (lane >> 4) & 1;

    float acc[4][4][4];
#pragma unroll
    for (int mt = 0; mt < 4; mt++)
#pragma unroll
        for (int nt = 0; nt < 4; nt++)
#pragma unroll
            for (int j = 0; j < 4; j++) acc[mt][nt][j] = 0.f;

    uint4 e0, e1, t0, t1;
    uint4 rB[8];
    t0 = make_uint4(0, 0, 0, 0); t1 = t0;

    {
        const int k0 = kc * KC;
        int ai = (k0 >> 3) + aseg * 2;
        e0 = __ldcg(pe + ai); e1 = __ldcg(pe + ai + 1);
        if (mode == 0) { t0 = __ldcg(pt + ai); t1 = __ldcg(pt + ai + 1); }
#pragma unroll
        for (int p = 0; p < 8; p++) {
            int v = p * 32 + vB;
            rB[p] = *(const uint4*)(g_cbK + ((size_t)(f * V_ + v)) * D_ + k0 + chB * 8);
        }
    }

    for (int ks = 0; ks < KC / 64; ks++) {
        {
            uint4 o0, o1;
            if (mode == 0) {
                o0.x = 0x3F803F80u ^ (e0.x ^ t0.x); o0.y = 0x3F803F80u ^ (e0.y ^ t0.y);
                o0.z = 0x3F803F80u ^ (e0.z ^ t0.z); o0.w = 0x3F803F80u ^ (e0.w ^ t0.w);
                o1.x = 0x3F803F80u ^ (e1.x ^ t1.x); o1.y = 0x3F803F80u ^ (e1.y ^ t1.y);
                o1.z = 0x3F803F80u ^ (e1.z ^ t1.z); o1.w = 0x3F803F80u ^ (e1.w ^ t1.w);
            } else { o0 = e0; o1 = e1; }
            uint4* as = (uint4*)((uint32_t*)As + arow * 36 + aseg * 8);
            as[0] = o0; as[1] = o1;
#pragma unroll
            for (int p = 0; p < 8; p++)
                *(uint4*)((uint32_t*)Bs + (p * 32 + vB) * 36 + chB * 4) = rB[p];
        }
        __syncthreads();

        if (ks + 1 < KC / 64) {
            const int k0n = kc * KC + (ks + 1) * 64;
            int ai = (k0n >> 3) + aseg * 2;
            e0 = __ldcg(pe + ai); e1 = __ldcg(pe + ai + 1);
            if (mode == 0) { t0 = __ldcg(pt + ai); t1 = __ldcg(pt + ai + 1); }
#pragma unroll
            for (int p = 0; p < 8; p++) {
                int v = p * 32 + vB;
                rB[p] = *(const uint4*)(g_cbK + ((size_t)(f * V_ + v)) * D_ + k0n + chB * 8);
            }
        }

#pragma unroll
        for (int k16 = 0; k16 < 4; k16++) {
            const int colElem = k16 * 16 + laneColH * 8;
            uint32_t a[4][4], b[4][2];
#pragma unroll
            for (int mt = 0; mt < 4; mt++) {
                uint32_t ad = asBase + ((mt * 16 + laneRow) * 72 + colElem) * 2;
                ldsm_x4(a[mt][0], a[mt][1], a[mt][2], a[mt][3], ad);
            }
#pragma unroll
            for (int h = 0; h < 2; h++) {
                uint32_t bd = bsBase + ((w * 32 + h * 16 + laneRow) * 72 + colElem) * 2;
                ldsm_x4(b[2 * h][0], b[2 * h + 1][0], b[2 * h][1], b[2 * h + 1][1], bd);
            }
#pragma unroll
            for (int mt = 0; mt < 4; mt++)
#pragma unroll
                for (int nt = 0; nt < 4; nt++) mma16816(acc[mt][nt], a[mt], b[nt]);
        }
        __syncthreads();
    }
    float* op = g_simp + ((size_t)(kc * F_ + f) * B_) * V_;
#pragma unroll
    for (int mt = 0; mt < 4; mt++) {
        int r = mt * 16 + g;
#pragma unroll
        for (int nt = 0; nt < 4; nt++) {
            int c = w * 32 + nt * 8 + 2 * t;
            *(float2*)&op[(size_t)r * V_ + c]       = make_float2(acc[mt][nt][0], acc[mt][nt][1]);
            *(float2*)&op[(size_t)(r + 8) * V_ + c] = make_float2(acc[mt][nt][2], acc[mt][nt][3]);
        }
    }
}

// reduce partials -> g_sim + exact bf16 hi/lo split; 2 elems per thread
__device__ __forceinline__ void phase_reduce(int bid) {
#pragma unroll
    for (int q = 0; q < 2; q++) {
        int i = bid * 256 + threadIdx.x + q * (NB * 256);   // covers 65536
        float s = 0.f;
#pragma unroll
        for (int kc = 0; kc < KCH; kc++) s += __ldcg(&g_simp[(size_t)kc * (F_ * B_ * V_) + i]);
        g_sim[i] = s;
        int si = (int)s;
        g_Ah[i] = __float2bfloat16((float)(si & ~127));
        g_Al[i] = __float2bfloat16((float)(si & 127));
    }
}

// stage 3 for one (dt, f) tile
__device__ __forceinline__ void phase_update_tile(uint8_t* sm, int dt, int f) {
    __nv_bfloat16* Ahs = (__nv_bfloat16*)sm;                // 64 x 72
    __nv_bfloat16* Als = (__nv_bfloat16*)(sm + 9216);       // 64 x 72
    __nv_bfloat16* Bs  = (__nv_bfloat16*)(sm + 18432);      // 128 x 72
    const int d0 = dt * 128;
    const int tid = threadIdx.x;
    const int w = tid >> 5, lane = tid & 31, g = lane >> 2, t = lane & 3;
    const int arow = tid >> 2, aseg = tid & 3;
    const int dB = tid >> 3, chB = tid & 7;

    const uint32_t ahBase = (uint32_t)__cvta_generic_to_shared(Ahs);
    const uint32_t alBase = (uint32_t)__cvta_generic_to_shared(Als);
    const uint32_t bsBase = (uint32_t)__cvta_generic_to_shared(Bs);
    const int laneRow  = lane & 15;
    const int laneColH = (lane >> 4) & 1;

    float acc[4][2][4];
#pragma unroll
    for (int mt = 0; mt < 4; mt++)
#pragma unroll
        for (int nt = 0; nt < 2; nt++)
#pragma unroll
            for (int j = 0; j < 4; j++) acc[mt][nt][j] = 0.f;

    uint4 h0, h1, l0, l1;
    uint4 rB[4];
    {
        const int vv = aseg * 16;
        h0 = __ldcg((const uint4*)(g_Ah + ((size_t)f * B_ + arow) * V_ + vv));
        h1 = __ldcg((const uint4*)(g_Ah + ((size_t)f * B_ + arow) * V_ + vv + 8));
        l0 = __ldcg((const uint4*)(g_Al + ((size_t)f * B_ + arow) * V_ + vv));
        l1 = __ldcg((const uint4*)(g_Al + ((size_t)f * B_ + arow) * V_ + vv + 8));
#pragma unroll
        for (int p = 0; p < 4; p++) {
            int dl = p * 32 + dB;
            rB[p] = *(const uint4*)(g_cbD + ((size_t)(f * D_ + d0 + dl)) * V_ + chB * 8);
        }
    }

    for (int vs = 0; vs < 4; vs++) {
        {
            uint4* ah = (uint4*)((uint32_t*)Ahs + arow * 36 + aseg * 8);
            uint4* al = (uint4*)((uint32_t*)Als + arow * 36 + aseg * 8);
            ah[0] = h0; ah[1] = h1;
            al[0] = l0; al[1] = l1;
#pragma unroll
            for (int p = 0; p < 4; p++)
                *(uint4*)((uint32_t*)Bs + (p * 32 + dB) * 36 + chB * 4) = rB[p];
        }
        __syncthreads();

        if (vs + 1 < 4) {
            const int v0n = (vs + 1) * 64;
            const int vv = v0n + aseg * 16;
            h0 = __ldcg((const uint4*)(g_Ah + ((size_t)f * B_ + arow) * V_ + vv));
            h1 = __ldcg((const uint4*)(g_Ah + ((size_t)f * B_ + arow) * V_ + vv + 8));
            l0 = __ldcg((const uint4*)(g_Al + ((size_t)f * B_ + arow) * V_ + vv));
            l1 = __ldcg((const uint4*)(g_Al + ((size_t)f * B_ + arow) * V_ + vv + 8));
#pragma unroll
            for (int p = 0; p < 4; p++) {
                int dl = p * 32 + dB;
                rB[p] = *(const uint4*)(g_cbD + ((size_t)(f * D_ + d0 + dl)) * V_ + v0n + chB * 8);
            }
        }

#pragma unroll
        for (int k16 = 0; k16 < 4; k16++) {
            const int colElem = k16 * 16 + laneColH * 8;
            uint32_t fa[4][4], fl[4][4], b[2][2];
#pragma unroll
            for (int mt = 0; mt < 4; mt++) {
                uint32_t adh = ahBase + ((mt * 16 + laneRow) * 72 + colElem) * 2;
                uint32_t adl = alBase + ((mt * 16 + laneRow) * 72 + colElem) * 2;
                ldsm_x4(fa[mt][0], fa[mt][1], fa[mt][2], fa[mt][3], adh);
                ldsm_x4(fl[mt][0], fl[mt][1], fl[mt][2], fl[mt][3], adl);
            }
            {
                uint32_t bd = bsBase + ((w * 16 + laneRow) * 72 + colElem) * 2;
                ldsm_x4(b[0][0], b[1][0], b[0][1], b[1][1], bd);
            }
#pragma unroll
            for (int mt = 0; mt < 4; mt++)
#pragma unroll
                for (int nt = 0; nt < 2; nt++) {
                    mma16816(acc[mt][nt], fa[mt], b[nt]);
                    mma16816(acc[mt][nt], fl[mt], b[nt]);
                }
        }
        __syncthreads();
    }
#pragma unroll
    for (int mt = 0; mt < 4; mt++) {
        int r = mt * 16 + g;
#pragma unroll
        for (int nt = 0; nt < 2; nt++) {
            int d = d0 + w * 16 + nt * 8 + 2 * t;
            uint32_t s0 = __float_as_uint(acc[mt][nt][0]);
            uint32_t s1 = __float_as_uint(acc[mt][nt][1]);
            uint32_t s2 = __float_as_uint(acc[mt][nt][2]);
            uint32_t s3 = __float_as_uint(acc[mt][nt][3]);
            uint32_t w0 = 0x3F803F80u | ((s0 >> 16) & 0x8000u) | (s1 & 0x80000000u);
            uint32_t w1 = 0x3F803F80u | ((s2 >> 16) & 0x8000u) | (s3 & 0x80000000u);
            ((uint32_t*)g_est_bf)[(((size_t)r * F_ + f) * D_ + d) >> 1] = w0;
            ((uint32_t*)g_est_bf)[(((size_t)(r + 8) * F_ + f) * D_ + d) >> 1] = w1;
        }
    }
}

// ---------------- the persistent iteration kernel (one launch for all 10 iters) --------
__global__ void __launch_bounds__(256) k_iter() {
    __shared__ __align__(16) uint8_t sm[46080];   // union: sim(45KB) / update(36KB)
    const int bid = blockIdx.x;
    int lsense = 0;

    for (int it = 0; it < ITERS_; it++) {
        phase_total(bid);
        gbar(lsense);
        phase_sim(sm, bid, 0);
        gbar(lsense);
        phase_reduce(bid);
        gbar(lsense);
#pragma unroll 1
        for (int u = 0; u < 4; u++) {             // 512 tiles over 128 blocks
            int tile = u * NB + bid;
            phase_update_tile(sm, tile >> 2, tile & 3);
        }
        gbar(lsense);
    }
    phase_sim(sm, bid, 1);                        // final similarity
    gbar(lsense);
    phase_reduce(bid);
    gbar(lsense);                                 // 42 barriers total (even -> state restored)
}

// ---------------- outputs ----------------
__global__ void k_emit(float* __restrict__ out) {
    int i = blockIdx.x * blockDim.x + threadIdx.x;
    if (i >= B_ * F_ * D_ / 2) return;
    uint32_t w = ((const uint32_t*)g_est_bf)[i];
    float2 o;
    o.x = (w & 0x8000u) ? -1.f : 1.f;
    o.y = (w & 0x80000000u) ? -1.f : 1.f;
    ((float2*)out)[i] = o;
}

__global__ void k_outcome(float* __restrict__ out) {
    int warp = (blockIdx.x * blockDim.x + threadIdx.x) >> 5;
    int lane = threadIdx.x & 31;
    if (warp >= B_ * F_) return;
    int b = warp >> 2, f = warp & 3;
    const float* s = g_sim + ((size_t)(f * B_ + b)) * V_;
    float best = -1.f; int bi = 0;
#pragma unroll
    for (int j = 0; j < 8; j++) {
        int v = j * 32 + lane;
        float a = fabsf(s[v]);
        if (a > best) { best = a; bi = v; }
    }
#pragma unroll
    for (int off = 16; off; off >>= 1) {
        float ob = __shfl_down_sync(0xffffffffu, best, off);
        int   oi = __shfl_down_sync(0xffffffffu, bi, off);
        if (ob > best || (ob == best && oi < bi)) { best = ob; bi = oi; }
    }
    if (lane == 0) out[warp] = (float)bi;
}

// ---------------- host launch ----------------
extern "C" void kernel_launch(void* const* d_in, const int* in_sizes, int n_in,
                              void* d_out, int out_size) {
    const float *input = nullptr, *est0 = nullptr, *cb = nullptr;
    for (int i = 0; i < n_in; i++) {
        if      (in_sizes[i] == B_ * D_)        input = (const float*)d_in[i];
        else if (in_sizes[i] == B_ * F_ * D_)   est0  = (const float*)d_in[i];
        else if (in_sizes[i] == F_ * V_ * D_)   cb    = (const float*)d_in[i];
    }
    if (!input && n_in > 0) input = (const float*)d_in[0];
    if (!est0  && n_in > 1) est0  = (const float*)d_in[1];
    if (!cb    && n_in > 2) cb    = (const float*)d_in[2];

    { int n = B_ * D_ / 2;        k_sign_pairs<<<(n + 255) / 256, 256>>>(input, 0, n); }
    { int n = B_ * F_ * D_ / 2;   k_sign_pairs<<<(n + 255) / 256, 256>>>(est0, 1, n); }
    { int n = F_ * V_ * D_ / 2;   k_sign_pairs<<<(n + 255) / 256, 256>>>(cb, 2, n); }
    k_trans<<<dim3(D_ / 32, V_ / 32, F_), 256>>>(cb);

    k_iter<<<NB, 256>>>();                        // all 10 iterations + final sim/reduce

    float* out = (float*)d_out;
    { int n = (B_ * F_ * D_ / 2 + 255) / 256; k_emit<<<n, 256>>>(out); }
    if (out_size >= B_ * F_ * D_ + B_ * F_) {
        k_outcome<<<32, 256>>>(out + (size_t)B_ * F_ * D_);
    }
}

// round 9
// speedup vs baseline: 1.1702x; 1.1702x over previous
#include <cuda_runtime.h>
#include <cuda_bf16.h>
#include <stdint.h>

#define B_ 64
#define F_ 4
#define V_ 256
#define D_ 16384
#define ITERS_ 10
#define KCH 32               // split-K chunks for stage 2
#define KC (D_/KCH)          // 512 k per chunk

// ---------------- static device scratch (no runtime allocation) ----------------
__device__ __align__(16) __nv_bfloat16 g_in_bf [B_*D_];                 // input, +-1 bf16
__device__ __align__(16) __nv_bfloat16 g_est_bf[B_*F_*D_];              // current estimates, +-1 bf16
__device__ __align__(16) __nv_bfloat16 g_T_bf  [B_*D_];                 // input * prod_f est (+-1 bf16)
__device__ __align__(16) __nv_bfloat16 g_cbK   [(size_t)F_*V_*D_];      // codebook [f][v][d] bf16
__device__ __align__(16) __nv_bfloat16 g_cbD   [(size_t)F_*D_*V_];      // codebook [f][d][v] bf16
__device__ __align__(16) int           g_simi  [2][F_*B_*V_];           // sim accum (exact int), 2 buffers

// ---------------- mma.sync helper (bf16, fp32 accum — exact for our integer data) ----
__device__ __forceinline__ void mma16816(float c[4], const uint32_t a[4], const uint32_t b[2]) {
    asm volatile(
        "mma.sync.aligned.m16n8k16.row.col.f32.bf16.bf16.f32 "
        "{%0,%1,%2,%3},{%4,%5,%6,%7},{%8,%9},{%0,%1,%2,%3};\n"
        : "+f"(c[0]), "+f"(c[1]), "+f"(c[2]), "+f"(c[3])
        : "r"(a[0]), "r"(a[1]), "r"(a[2]), "r"(a[3]), "r"(b[0]), "r"(b[1]));
}

__device__ __forceinline__ void ldsm_x4(uint32_t& r0, uint32_t& r1, uint32_t& r2, uint32_t& r3,
                                        uint32_t saddr) {
    asm volatile("ldmatrix.sync.aligned.m8n8.x4.shared.b16 {%0,%1,%2,%3}, [%4];"
                 : "=r"(r0), "=r"(r1), "=r"(r2), "=r"(r3) : "r"(saddr));
}

// pack two ints' hi parts (si & ~127) as bf16x2 — exact (multiple of 128, |.|<=16384)
__device__ __forceinline__ uint32_t pack_hi(int a, int b) {
    uint32_t ha = (uint32_t)__bfloat16_as_ushort(__float2bfloat16((float)(a & ~127)));
    uint32_t hb = (uint32_t)__bfloat16_as_ushort(__float2bfloat16((float)(b & ~127)));
    return ha | (hb << 16);
}
// pack two ints' lo parts (si & 127) as bf16x2 — exact (0..127)
__device__ __forceinline__ uint32_t pack_lo(int a, int b) {
    uint32_t la = (uint32_t)__bfloat16_as_ushort(__float2bfloat16((float)(a & 127)));
    uint32_t lb = (uint32_t)__bfloat16_as_ushort(__float2bfloat16((float)(b & 127)));
    return la | (lb << 16);
}

// ---------------- conversion kernels ----------------
__global__ void k_sign_pairs(const float* __restrict__ src, int which, int npairs) {
    int i = blockIdx.x * blockDim.x + threadIdx.x;
    if (i >= npairs) return;
    uint2 u = ((const uint2*)src)[i];
    uint32_t w = 0x3F803F80u | ((u.x >> 16) & 0x8000u) | (u.y & 0x80000000u);
    uint32_t* dst = (which == 0) ? (uint32_t*)g_in_bf
                  : (which == 1) ? (uint32_t*)g_est_bf
                                 : (uint32_t*)g_cbK;
    dst[i] = w;
}

__global__ void k_trans(const float* __restrict__ cb) {
    __shared__ unsigned short ts[32][33];
    int f = blockIdx.z, d0 = blockIdx.x * 32, v0 = blockIdx.y * 32;
    int tx = threadIdx.x & 31, ty = threadIdx.x >> 5;  // 32 x 8
#pragma unroll
    for (int r = 0; r < 4; r++) {
        int v = v0 + ty + r * 8;
        uint32_t ub = __float_as_uint(cb[((size_t)(f * V_ + v)) * D_ + d0 + tx]);
        ts[ty + r * 8][tx] = (unsigned short)(0x3F80u | ((ub >> 16) & 0x8000u));
    }
    __syncthreads();
#pragma unroll
    for (int r = 0; r < 4; r++) {
        int d = d0 + ty + r * 8;
        ((unsigned short*)g_cbD)[((size_t)(f * D_ + d)) * V_ + v0 + tx] = ts[tx][ty + r * 8];
    }
}

__global__ void k_zero() {       // zero both sim buffers (2 * 65536 ints = 32768 int4)
    int i = blockIdx.x * blockDim.x + threadIdx.x;
    ((int4*)g_simi)[i] = make_int4(0, 0, 0, 0);
}

// ---------------- per-iter: T = input * est0 * est1 * est2 * est3 (bf16 XOR) -----------
__global__ void k_totalbf() {
    int i = blockIdx.x * blockDim.x + threadIdx.x;     // uint4 over B_*D_ bf16 elements
    int e0 = i * 8;
    int b = e0 / D_, d = e0 % D_;
    uint4 t = *(const uint4*)(g_in_bf + (size_t)b * D_ + d);
#pragma unroll
    for (int ff = 0; ff < F_; ff++) {
        uint4 e = *(const uint4*)(g_est_bf + ((size_t)b * F_ + ff) * D_ + d);
        t.x ^= e.x; t.y ^= e.y; t.z ^= e.z; t.w ^= e.w;
    }
    *(uint4*)(g_T_bf + (size_t)b * D_ + d) = t;
}

// ---------------- stage 2: sim[f][b][v] += sum_d n * cb (int atomics, exact) ------------
// mode 0: n = T ^ est_f; mode 1: n = est_f. Accumulates into g_simi[p].
__global__ void __launch_bounds__(256) k_sim(int mode, int p) {
    __shared__ __align__(16) __nv_bfloat16 As[64 * 72];
    __shared__ __align__(16) __nv_bfloat16 Bs[256 * 72];
    const int kc = blockIdx.x, f = blockIdx.y;
    const int tid = threadIdx.x;
    const int w = tid >> 5, lane = tid & 31, g = lane >> 2, t = lane & 3;
    const int arow = tid >> 2, aseg = tid & 3;
    const int vB = tid >> 3, chB = tid & 7;

    const uint4* pe = (const uint4*)(g_est_bf + ((size_t)arow * F_ + f) * D_);
    const uint4* pt = (const uint4*)(g_T_bf + (size_t)arow * D_);

    const uint32_t asBase = (uint32_t)__cvta_generic_to_shared(As);
    const uint32_t bsBase = (uint32_t)__cvta_generic_to_shared(Bs);
    const int laneRow  = lane & 15;
    const int laneColH = (lane >> 4) & 1;

    float acc[4][4][4];
#pragma unroll
    for (int mt = 0; mt < 4; mt++)
#pragma unroll
        for (int nt = 0; nt < 4; nt++)
#pragma unroll
            for (int j = 0; j < 4; j++) acc[mt][nt][j] = 0.f;

    uint4 e0, e1, t0, t1;
    uint4 rB[8];
    t0 = make_uint4(0, 0, 0, 0); t1 = t0;

    {
        const int k0 = kc * KC;
        int ai = (k0 >> 3) + aseg * 2;
        e0 = pe[ai]; e1 = pe[ai + 1];
        if (mode == 0) { t0 = pt[ai]; t1 = pt[ai + 1]; }
#pragma unroll
        for (int pq = 0; pq < 8; pq++) {
            int v = pq * 32 + vB;
            rB[pq] = *(const uint4*)(g_cbK + ((size_t)(f * V_ + v)) * D_ + k0 + chB * 8);
        }
    }

    for (int ks = 0; ks < KC / 64; ks++) {
        {
            uint4 o0, o1;
            if (mode == 0) {
                o0.x = 0x3F803F80u ^ (e0.x ^ t0.x); o0.y = 0x3F803F80u ^ (e0.y ^ t0.y);
                o0.z = 0x3F803F80u ^ (e0.z ^ t0.z); o0.w = 0x3F803F80u ^ (e0.w ^ t0.w);
                o1.x = 0x3F803F80u ^ (e1.x ^ t1.x); o1.y = 0x3F803F80u ^ (e1.y ^ t1.y);
                o1.z = 0x3F803F80u ^ (e1.z ^ t1.z); o1.w = 0x3F803F80u ^ (e1.w ^ t1.w);
            } else { o0 = e0; o1 = e1; }
            uint4* as = (uint4*)((uint32_t*)As + arow * 36 + aseg * 8);
            as[0] = o0; as[1] = o1;
#pragma unroll
            for (int pq = 0; pq < 8; pq++)
                *(uint4*)((uint32_t*)Bs + (pq * 32 + vB) * 36 + chB * 4) = rB[pq];
        }
        __syncthreads();

        if (ks + 1 < KC / 64) {
            const int k0n = kc * KC + (ks + 1) * 64;
            int ai = (k0n >> 3) + aseg * 2;
            e0 = pe[ai]; e1 = pe[ai + 1];
            if (mode == 0) { t0 = pt[ai]; t1 = pt[ai + 1]; }
#pragma unroll
            for (int pq = 0; pq < 8; pq++) {
                int v = pq * 32 + vB;
                rB[pq] = *(const uint4*)(g_cbK + ((size_t)(f * V_ + v)) * D_ + k0n + chB * 8);
            }
        }

#pragma unroll
        for (int k16 = 0; k16 < 4; k16++) {
            const int colElem = k16 * 16 + laneColH * 8;
            uint32_t a[4][4], b[4][2];
#pragma unroll
            for (int mt = 0; mt < 4; mt++) {
                uint32_t ad = asBase + ((mt * 16 + laneRow) * 72 + colElem) * 2;
                ldsm_x4(a[mt][0], a[mt][1], a[mt][2], a[mt][3], ad);
            }
#pragma unroll
            for (int h = 0; h < 2; h++) {
                uint32_t bd = bsBase + ((w * 32 + h * 16 + laneRow) * 72 + colElem) * 2;
                ldsm_x4(b[2 * h][0], b[2 * h + 1][0], b[2 * h][1], b[2 * h + 1][1], bd);
            }
#pragma unroll
            for (int mt = 0; mt < 4; mt++)
#pragma unroll
                for (int nt = 0; nt < 4; nt++) mma16816(acc[mt][nt], a[mt], b[nt]);
        }
        __syncthreads();
    }
    // --- epilogue: exact integer atomics into g_simi[p] (order-independent) ---
    int* op = g_simi[p] + (size_t)f * B_ * V_;
#pragma unroll
    for (int mt = 0; mt < 4; mt++) {
        int r = mt * 16 + g;
#pragma unroll
        for (int nt = 0; nt < 4; nt++) {
            int c = w * 32 + nt * 8 + 2 * t;
            atomicAdd(&op[(size_t)r * V_ + c],           (int)acc[mt][nt][0]);
            atomicAdd(&op[(size_t)r * V_ + c + 1],       (int)acc[mt][nt][1]);
            atomicAdd(&op[(size_t)(r + 8) * V_ + c],     (int)acc[mt][nt][2]);
            atomicAdd(&op[(size_t)(r + 8) * V_ + c + 1], (int)acc[mt][nt][3]);
        }
    }
}

// ---------------- stage 3: est = sign( sum_v sim * cbD ); reads g_simi[p], splits hi/lo
// in the A loader; zeroes g_simi[p^1] for the next iteration.
__global__ void __launch_bounds__(256) k_update(int p) {
    __shared__ __align__(16) __nv_bfloat16 Bs[128 * 72];
    __shared__ __align__(16) __nv_bfloat16 Ahs[64 * 72];
    __shared__ __align__(16) __nv_bfloat16 Als[64 * 72];
    const int dt = blockIdx.x, f = blockIdx.y;
    const int d0 = dt * 128;
    const int tid = threadIdx.x;
    const int w = tid >> 5, lane = tid & 31, g = lane >> 2, t = lane & 3;
    const int arow = tid >> 2, aseg = tid & 3;
    const int dB = tid >> 3, chB = tid & 7;

    // zero next-iteration sim buffer (disjoint 128-int slices; no sync needed)
    {
        int bl = blockIdx.y * (D_ / 128) + blockIdx.x;   // 0..511
        if (tid < 32) ((int4*)g_simi[p ^ 1])[bl * 32 + tid] = make_int4(0, 0, 0, 0);
    }

    const uint32_t ahBase = (uint32_t)__cvta_generic_to_shared(Ahs);
    const uint32_t alBase = (uint32_t)__cvta_generic_to_shared(Als);
    const uint32_t bsBase = (uint32_t)__cvta_generic_to_shared(Bs);
    const int laneRow  = lane & 15;
    const int laneColH = (lane >> 4) & 1;

    float acc[4][2][4];
#pragma unroll
    for (int mt = 0; mt < 4; mt++)
#pragma unroll
        for (int nt = 0; nt < 2; nt++)
#pragma unroll
            for (int j = 0; j < 4; j++) acc[mt][nt][j] = 0.f;

    const int4* ps = (const int4*)(g_simi[p] + ((size_t)f * B_ + arow) * V_);
    int4 s0, s1, s2, s3;        // 16 ints (this thread's 16 v-values)
    uint4 rB[4];

    {   // preload vs=0
        const int vi = (aseg * 16) >> 2;
        s0 = ps[vi]; s1 = ps[vi + 1]; s2 = ps[vi + 2]; s3 = ps[vi + 3];
#pragma unroll
        for (int pq = 0; pq < 4; pq++) {
            int dl = pq * 32 + dB;
            rB[pq] = *(const uint4*)(g_cbD + ((size_t)(f * D_ + d0 + dl)) * V_ + chB * 8);
        }
    }

    for (int vs = 0; vs < 4; vs++) {
        {   // split + store current tiles
            uint4 h0, h1, l0, l1;
            h0.x = pack_hi(s0.x, s0.y); h0.y = pack_hi(s0.z, s0.w);
            h0.z = pack_hi(s1.x, s1.y); h0.w = pack_hi(s1.z, s1.w);
            h1.x = pack_hi(s2.x, s2.y); h1.y = pack_hi(s2.z, s2.w);
            h1.z = pack_hi(s3.x, s3.y); h1.w = pack_hi(s3.z, s3.w);
            l0.x = pack_lo(s0.x, s0.y); l0.y = pack_lo(s0.z, s0.w);
            l0.z = pack_lo(s1.x, s1.y); l0.w = pack_lo(s1.z, s1.w);
            l1.x = pack_lo(s2.x, s2.y); l1.y = pack_lo(s2.z, s2.w);
            l1.z = pack_lo(s3.x, s3.y); l1.w = pack_lo(s3.z, s3.w);
            uint4* ah = (uint4*)((uint32_t*)Ahs + arow * 36 + aseg * 8);
            uint4* al = (uint4*)((uint32_t*)Als + arow * 36 + aseg * 8);
            ah[0] = h0; ah[1] = h1;
            al[0] = l0; al[1] = l1;
#pragma unroll
            for (int pq = 0; pq < 4; pq++)
                *(uint4*)((uint32_t*)Bs + (pq * 32 + dB) * 36 + chB * 4) = rB[pq];
        }
        __syncthreads();

        if (vs + 1 < 4) {   // prefetch next chunk
            const int v0n = (vs + 1) * 64;
            const int vi = (v0n + aseg * 16) >> 2;
            s0 = ps[vi]; s1 = ps[vi + 1]; s2 = ps[vi + 2]; s3 = ps[vi + 3];
#pragma unroll
            for (int pq = 0; pq < 4; pq++) {
                int dl = pq * 32 + dB;
                rB[pq] = *(const uint4*)(g_cbD + ((size_t)(f * D_ + d0 + dl)) * V_ + v0n + chB * 8);
            }
        }

#pragma unroll
        for (int k16 = 0; k16 < 4; k16++) {
            const int colElem = k16 * 16 + laneColH * 8;
            uint32_t fa[4][4], fl[4][4], b[2][2];
#pragma unroll
            for (int mt = 0; mt < 4; mt++) {
                uint32_t adh = ahBase + ((mt * 16 + laneRow) * 72 + colElem) * 2;
                uint32_t adl = alBase + ((mt * 16 + laneRow) * 72 + colElem) * 2;
                ldsm_x4(fa[mt][0], fa[mt][1], fa[mt][2], fa[mt][3], adh);
                ldsm_x4(fl[mt][0], fl[mt][1], fl[mt][2], fl[mt][3], adl);
            }
            {
                uint32_t bd = bsBase + ((w * 16 + laneRow) * 72 + colElem) * 2;
                ldsm_x4(b[0][0], b[1][0], b[0][1], b[1][1], bd);
            }
#pragma unroll
            for (int mt = 0; mt < 4; mt++)
#pragma unroll
                for (int nt = 0; nt < 2; nt++) {
                    mma16816(acc[mt][nt], fa[mt], b[nt]);
                    mma16816(acc[mt][nt], fl[mt], b[nt]);
                }
        }
        __syncthreads();
    }
    // epilogue: sign(acc) -> +-1 bf16 into g_est_bf
#pragma unroll
    for (int mt = 0; mt < 4; mt++) {
        int r = mt * 16 + g;
#pragma unroll
        for (int nt = 0; nt < 2; nt++) {
            int d = d0 + w * 16 + nt * 8 + 2 * t;
            uint32_t s0u = __float_as_uint(acc[mt][nt][0]);
            uint32_t s1u = __float_as_uint(acc[mt][nt][1]);
            uint32_t s2u = __float_as_uint(acc[mt][nt][2]);
            uint32_t s3u = __float_as_uint(acc[mt][nt][3]);
            uint32_t w0 = 0x3F803F80u | ((s0u >> 16) & 0x8000u) | (s1u & 0x80000000u);
            uint32_t w1 = 0x3F803F80u | ((s2u >> 16) & 0x8000u) | (s3u & 0x80000000u);
            ((uint32_t*)g_est_bf)[(((size_t)r * F_ + f) * D_ + d) >> 1] = w0;
            ((uint32_t*)g_est_bf)[(((size_t)(r + 8) * F_ + f) * D_ + d) >> 1] = w1;
        }
    }
}

// ---------------- outputs ----------------
__global__ void k_emit(float* __restrict__ out) {
    int i = blockIdx.x * blockDim.x + threadIdx.x;
    if (i >= B_ * F_ * D_ / 2) return;
    uint32_t w = ((const uint32_t*)g_est_bf)[i];
    float2 o;
    o.x = (w & 0x8000u) ? -1.f : 1.f;
    o.y = (w & 0x80000000u) ? -1.f : 1.f;
    ((float2*)out)[i] = o;
}

__global__ void k_outcome(float* __restrict__ out) {
    int warp = (blockIdx.x * blockDim.x + threadIdx.x) >> 5;
    int lane = threadIdx.x & 31;
    if (warp >= B_ * F_) return;
    int b = warp >> 2, f = warp & 3;
    const int* s = g_simi[ITERS_ & 1] + ((size_t)(f * B_ + b)) * V_;
    int best = -1, bi = 0;
#pragma unroll
    for (int j = 0; j < 8; j++) {
        int v = j * 32 + lane;
        int sv = s[v];
        int a = sv < 0 ? -sv : sv;
        if (a > best) { best = a; bi = v; }     // ascending v: strict > keeps first
    }
#pragma unroll
    for (int off = 16; off; off >>= 1) {
        int ob = __shfl_down_sync(0xffffffffu, best, off);
        int oi = __shfl_down_sync(0xffffffffu, bi, off);
        if (ob > best || (ob == best && oi < bi)) { best = ob; bi = oi; }
    }
    if (lane == 0) out[warp] = (float)bi;       // outcome[b][f], first-max index
}

// ---------------- host launch ----------------
extern "C" void kernel_launch(void* const* d_in, const int* in_sizes, int n_in,
                              void* d_out, int out_size) {
    const float *input = nullptr, *est0 = nullptr, *cb = nullptr;
    for (int i = 0; i < n_in; i++) {
        if      (in_sizes[i] == B_ * D_)        input = (const float*)d_in[i];
        else if (in_sizes[i] == B_ * F_ * D_)   est0  = (const float*)d_in[i];
        else if (in_sizes[i] == F_ * V_ * D_)   cb    = (const float*)d_in[i];
    }
    if (!input && n_in > 0) input = (const float*)d_in[0];
    if (!est0  && n_in > 1) est0  = (const float*)d_in[1];
    if (!cb    && n_in > 2) cb    = (const float*)d_in[2];

    { int n = B_ * D_ / 2;        k_sign_pairs<<<(n + 255) / 256, 256>>>(input, 0, n); }
    { int n = B_ * F_ * D_ / 2;   k_sign_pairs<<<(n + 255) / 256, 256>>>(est0, 1, n); }
    { int n = F_ * V_ * D_ / 2;   k_sign_pairs<<<(n + 255) / 256, 256>>>(cb, 2, n); }
    k_trans<<<dim3(D_ / 32, V_ / 32, F_), 256>>>(cb);
    k_zero<<<128, 256>>>();                      // zero both sim buffers

    for (int it = 0; it < ITERS_; it++) {
        int p = it & 1;
        k_totalbf<<<B_ * D_ / 8 / 256, 256>>>();
        k_sim<<<dim3(KCH, F_), 256>>>(0, p);
        k_update<<<dim3(D_ / 128, F_), 256>>>(p);   // also zeroes buffer p^1
    }
    // final similarity on converged estimates (buffer ITERS_&1 = 0, zeroed by update it=9)
    k_sim<<<dim3(KCH, F_), 256>>>(1, ITERS_ & 1);

    float* out = (float*)d_out;
    { int n = (B_ * F_ * D_ / 2 + 255) / 256; k_emit<<<n, 256>>>(out); }
    if (out_size >= B_ * F_ * D_ + B_ * F_) {
        k_outcome<<<32, 256>>>(out + (size_t)B_ * F_ * D_);
    }
}

// round 10
// speedup vs baseline: 1.2897x; 1.1021x over previous
#include <cuda_runtime.h>
#include <cuda_bf16.h>
#include <stdint.h>

#define B_ 64
#define F_ 4
#define V_ 256
#define D_ 16384
#define ITERS_ 10
#define KCH 32               // split-K chunks for stage 2
#define KC (D_/KCH)          // 512 k per chunk

// ---------------- static device scratch (no runtime allocation) ----------------
__device__ __align__(16) __nv_bfloat16 g_in_bf [B_*D_];                 // input, +-1 bf16
__device__ __align__(16) __nv_bfloat16 g_est_bf[B_*F_*D_];              // current estimates, +-1 bf16
__device__ __align__(16) __nv_bfloat16 g_cbK   [(size_t)F_*V_*D_];      // codebook [f][v][d] bf16
__device__ __align__(16) __nv_bfloat16 g_cbD   [(size_t)F_*D_*V_];      // codebook [f][d][v] bf16
__device__ __align__(16) float         g_simp  [(size_t)KCH*F_*B_*V_];  // split-K partials
__device__ __align__(16) float         g_sim   [F_*B_*V_];              // reduced sim (exact ints)
__device__ __align__(16) __nv_bfloat16 g_Ah    [F_*B_*V_];              // sim & ~127 (exact bf16)
__device__ __align__(16) __nv_bfloat16 g_Al    [F_*B_*V_];              // sim &  127 (exact bf16)

// ---------------- mma.sync helper (bf16, fp32 accum — exact for our integer data) ----
__device__ __forceinline__ void mma16816(float c[4], const uint32_t a[4], const uint32_t b[2]) {
    asm volatile(
        "mma.sync.aligned.m16n8k16.row.col.f32.bf16.bf16.f32 "
        "{%0,%1,%2,%3},{%4,%5,%6,%7},{%8,%9},{%0,%1,%2,%3};\n"
        : "+f"(c[0]), "+f"(c[1]), "+f"(c[2]), "+f"(c[3])
        : "r"(a[0]), "r"(a[1]), "r"(a[2]), "r"(a[3]), "r"(b[0]), "r"(b[1]));
}

__device__ __forceinline__ void ldsm_x4(uint32_t& r0, uint32_t& r1, uint32_t& r2, uint32_t& r3,
                                        uint32_t saddr) {
    asm volatile("ldmatrix.sync.aligned.m8n8.x4.shared.b16 {%0,%1,%2,%3}, [%4];"
                 : "=r"(r0), "=r"(r1), "=r"(r2), "=r"(r3) : "r"(saddr));
}

// ---------------- setup: input + est signs in ONE launch ----------------
#define NPAIRS_IN  (B_*D_/2)        // 524288
#define NPAIRS_EST (B_*F_*D_/2)     // 2097152
__global__ void k_signs(const float* __restrict__ input, const float* __restrict__ est0) {
    int i = blockIdx.x * blockDim.x + threadIdx.x;
    if (i < NPAIRS_IN) {
        uint2 u = ((const uint2*)input)[i];
        ((uint32_t*)g_in_bf)[i] = 0x3F803F80u | ((u.x >> 16) & 0x8000u) | (u.y & 0x80000000u);
    } else {
        int j = i - NPAIRS_IN;
        if (j < NPAIRS_EST) {
            uint2 u = ((const uint2*)est0)[j];
            ((uint32_t*)g_est_bf)[j] = 0x3F803F80u | ((u.x >> 16) & 0x8000u) | (u.y & 0x80000000u);
        }
    }
}

// ---------------- setup: codebook -> cbK AND cbD from a single fp32 read -------------
__global__ void k_cb(const float* __restrict__ cb) {
    __shared__ unsigned short ts[32][33];
    int f = blockIdx.z, d0 = blockIdx.x * 32, v0 = blockIdx.y * 32;
    int tx = threadIdx.x & 31, ty = threadIdx.x >> 5;  // 32 x 8
#pragma unroll
    for (int r = 0; r < 4; r++) {
        int v = v0 + ty + r * 8;
        uint32_t ub = __float_as_uint(cb[((size_t)(f * V_ + v)) * D_ + d0 + tx]);
        unsigned short s = (unsigned short)(0x3F80u | ((ub >> 16) & 0x8000u));
        ts[ty + r * 8][tx] = s;
        ((unsigned short*)g_cbK)[((size_t)(f * V_ + v)) * D_ + d0 + tx] = s;   // row-major
    }
    __syncthreads();
#pragma unroll
    for (int r = 0; r < 4; r++) {
        int d = d0 + ty + r * 8;
        ((unsigned short*)g_cbD)[((size_t)(f * D_ + d)) * V_ + v0 + tx] = ts[tx][ty + r * 8];
    }
}

// ---------------- stage 2: sim[f][b][v] = sum_d n * cb -------------------------------
// mode 0: n = input * prod(est) * est_f, computed inline in the A-prefetch (6-word XOR,
// magnitudes cancel -> restore 0x3F803F80). mode 1: n = est_f.
__global__ void __launch_bounds__(256) k_sim(int mode) {
    __shared__ __align__(16) __nv_bfloat16 As[64 * 72];
    __shared__ __align__(16) __nv_bfloat16 Bs[256 * 72];
    const int kc = blockIdx.x, f = blockIdx.y;
    const int tid = threadIdx.x;
    const int w = tid >> 5, lane = tid & 31, g = lane >> 2, t = lane & 3;
    const int arow = tid >> 2, aseg = tid & 3;
    const int vB = tid >> 3, chB = tid & 7;

    const uint4* pin = (const uint4*)(g_in_bf + (size_t)arow * D_);
    const uint4* pef = (const uint4*)(g_est_bf + ((size_t)arow * F_ + f) * D_);

    const uint32_t asBase = (uint32_t)__cvta_generic_to_shared(As);
    const uint32_t bsBase = (uint32_t)__cvta_generic_to_shared(Bs);
    const int laneRow  = lane & 15;
    const int laneColH = (lane >> 4) & 1;

    float acc[4][4][4];
#pragma unroll
    for (int mt = 0; mt < 4; mt++)
#pragma unroll
        for (int nt = 0; nt < 4; nt++)
#pragma unroll
            for (int j = 0; j < 4; j++) acc[mt][nt][j] = 0.f;

    uint4 a0, a1;                              // final A words (prefetched+computed)
    uint4 rB[8];                               // B prefetch regs

    // ---- A prefetch/compute for a given k-offset ----
    auto prefetchA = [&](int k0, uint4& o0, uint4& o1) {
        int ai = (k0 >> 3) + aseg * 2;
        if (mode == 0) {
            uint4 x0 = pin[ai], x1 = pin[ai + 1];
            uint4 f0 = make_uint4(0, 0, 0, 0), f1 = f0;
#pragma unroll
            for (int ff = 0; ff < F_; ff++) {
                const uint4* pe = (const uint4*)(g_est_bf + ((size_t)arow * F_ + ff) * D_);
                uint4 e0 = pe[ai], e1 = pe[ai + 1];
                x0.x ^= e0.x; x0.y ^= e0.y; x0.z ^= e0.z; x0.w ^= e0.w;
                x1.x ^= e1.x; x1.y ^= e1.y; x1.z ^= e1.z; x1.w ^= e1.w;
                if (ff == f) { f0 = e0; f1 = e1; }
            }
            // est_f appears twice (total product and unbound factor) -> xor again
            x0.x ^= f0.x; x0.y ^= f0.y; x0.z ^= f0.z; x0.w ^= f0.w;
            x1.x ^= f1.x; x1.y ^= f1.y; x1.z ^= f1.z; x1.w ^= f1.w;
            // 6 valid +-1 bf16 words XORed -> magnitude bits cancel; restore
            o0.x = 0x3F803F80u ^ x0.x; o0.y = 0x3F803F80u ^ x0.y;
            o0.z = 0x3F803F80u ^ x0.z; o0.w = 0x3F803F80u ^ x0.w;
            o1.x = 0x3F803F80u ^ x1.x; o1.y = 0x3F803F80u ^ x1.y;
            o1.z = 0x3F803F80u ^ x1.z; o1.w = 0x3F803F80u ^ x1.w;
        } else {
            o0 = pef[ai]; o1 = pef[ai + 1];
        }
    };

    // preload ks=0
    {
        const int k0 = kc * KC;
        prefetchA(k0, a0, a1);
#pragma unroll
        for (int p = 0; p < 8; p++) {
            int v = p * 32 + vB;
            rB[p] = *(const uint4*)(g_cbK + ((size_t)(f * V_ + v)) * D_ + k0 + chB * 8);
        }
    }

    for (int ks = 0; ks < KC / 64; ks++) {
        // ---- store current tile from regs ----
        {
            uint4* as = (uint4*)((uint32_t*)As + arow * 36 + aseg * 8);
            as[0] = a0; as[1] = a1;
#pragma unroll
            for (int p = 0; p < 8; p++)
                *(uint4*)((uint32_t*)Bs + (p * 32 + vB) * 36 + chB * 4) = rB[p];
        }
        __syncthreads();

        // ---- prefetch next tile (overlapped with mma below) ----
        if (ks + 1 < KC / 64) {
            const int k0n = kc * KC + (ks + 1) * 64;
            prefetchA(k0n, a0, a1);
#pragma unroll
            for (int p = 0; p < 8; p++) {
                int v = p * 32 + vB;
                rB[p] = *(const uint4*)(g_cbK + ((size_t)(f * V_ + v)) * D_ + k0n + chB * 8);
            }
        }

        // ---- mma over 4 k16 steps (ldmatrix fragments) ----
#pragma unroll
        for (int k16 = 0; k16 < 4; k16++) {
            const int colElem = k16 * 16 + laneColH * 8;
            uint32_t a[4][4], b[4][2];
#pragma unroll
            for (int mt = 0; mt < 4; mt++) {
                uint32_t ad = asBase + ((mt * 16 + laneRow) * 72 + colElem) * 2;
                ldsm_x4(a[mt][0], a[mt][1], a[mt][2], a[mt][3], ad);
            }
#pragma unroll
            for (int h = 0; h < 2; h++) {
                uint32_t bd = bsBase + ((w * 32 + h * 16 + laneRow) * 72 + colElem) * 2;
                ldsm_x4(b[2 * h][0], b[2 * h + 1][0], b[2 * h][1], b[2 * h + 1][1], bd);
            }
#pragma unroll
            for (int mt = 0; mt < 4; mt++)
#pragma unroll
                for (int nt = 0; nt < 4; nt++) mma16816(acc[mt][nt], a[mt], b[nt]);
        }
        __syncthreads();
    }
    // --- write split-K partials ---
    float* op = g_simp + ((size_t)(kc * F_ + f) * B_) * V_;
#pragma unroll
    for (int mt = 0; mt < 4; mt++) {
        int r = mt * 16 + g;
#pragma unroll
        for (int nt = 0; nt < 4; nt++) {
            int c = w * 32 + nt * 8 + 2 * t;
            *(float2*)&op[(size_t)r * V_ + c]       = make_float2(acc[mt][nt][0], acc[mt][nt][1]);
            *(float2*)&op[(size_t)(r + 8) * V_ + c] = make_float2(acc[mt][nt][2], acc[mt][nt][3]);
        }
    }
}

// ---------------- reduce partials, emit exact bf16 split of sim ----------------
__global__ void k_reduce() {
    int i = blockIdx.x * blockDim.x + threadIdx.x;  // F_*B_*V_ = 65536
    float s = 0.f;
#pragma unroll
    for (int kc = 0; kc < KCH; kc++) s += g_simp[(size_t)kc * (F_ * B_ * V_) + i];
    g_sim[i] = s;
    int si = (int)s;                       // exact integer
    g_Ah[i] = __float2bfloat16((float)(si & ~127));  // multiple of 128 -> exact bf16
    g_Al[i] = __float2bfloat16((float)(si & 127));   // 0..127 -> exact bf16
}

// ---------------- stage 3: est = sign( sum_v sim * cbD ) ----------------
__global__ void __launch_bounds__(256) k_update() {
    __shared__ __align__(16) __nv_bfloat16 Bs[128 * 72];
    __shared__ __align__(16) __nv_bfloat16 Ahs[64 * 72];
    __shared__ __align__(16) __nv_bfloat16 Als[64 * 72];
    const int dt = blockIdx.x, f = blockIdx.y;
    const int d0 = dt * 128;
    const int tid = threadIdx.x;
    const int w = tid >> 5, lane = tid & 31, g = lane >> 2, t = lane & 3;
    const int arow = tid >> 2, aseg = tid & 3;
    const int dB = tid >> 3, chB = tid & 7;

    const uint32_t ahBase = (uint32_t)__cvta_generic_to_shared(Ahs);
    const uint32_t alBase = (uint32_t)__cvta_generic_to_shared(Als);
    const uint32_t bsBase = (uint32_t)__cvta_generic_to_shared(Bs);
    const int laneRow  = lane & 15;
    const int laneColH = (lane >> 4) & 1;

    float acc[4][2][4];
#pragma unroll
    for (int mt = 0; mt < 4; mt++)
#pragma unroll
        for (int nt = 0; nt < 2; nt++)
#pragma unroll
            for (int j = 0; j < 4; j++) acc[mt][nt][j] = 0.f;

    uint4 h0, h1, l0, l1;
    uint4 rB[4];
    {
        const int vv = aseg * 16;
        h0 = *(const uint4*)(g_Ah + ((size_t)f * B_ + arow) * V_ + vv);
        h1 = *(const uint4*)(g_Ah + ((size_t)f * B_ + arow) * V_ + vv + 8);
        l0 = *(const uint4*)(g_Al + ((size_t)f * B_ + arow) * V_ + vv);
        l1 = *(const uint4*)(g_Al + ((size_t)f * B_ + arow) * V_ + vv + 8);
#pragma unroll
        for (int p = 0; p < 4; p++) {
            int dl = p * 32 + dB;
            rB[p] = *(const uint4*)(g_cbD + ((size_t)(f * D_ + d0 + dl)) * V_ + chB * 8);
        }
    }

    for (int vs = 0; vs < 4; vs++) {
        {
            uint4* ah = (uint4*)((uint32_t*)Ahs + arow * 36 + aseg * 8);
            uint4* al = (uint4*)((uint32_t*)Als + arow * 36 + aseg * 8);
            ah[0] = h0; ah[1] = h1;
            al[0] = l0; al[1] = l1;
#pragma unroll
            for (int p = 0; p < 4; p++)
                *(uint4*)((uint32_t*)Bs + (p * 32 + dB) * 36 + chB * 4) = rB[p];
        }
        __syncthreads();

        if (vs + 1 < 4) {
            const int v0n = (vs + 1) * 64;
            const int vv = v0n + aseg * 16;
            h0 = *(const uint4*)(g_Ah + ((size_t)f * B_ + arow) * V_ + vv);
            h1 = *(const uint4*)(g_Ah + ((size_t)f * B_ + arow) * V_ + vv + 8);
            l0 = *(const uint4*)(g_Al + ((size_t)f * B_ + arow) * V_ + vv);
            l1 = *(const uint4*)(g_Al + ((size_t)f * B_ + arow) * V_ + vv + 8);
#pragma unroll
            for (int p = 0; p < 4; p++) {
                int dl = p * 32 + dB;
                rB[p] = *(const uint4*)(g_cbD + ((size_t)(f * D_ + d0 + dl)) * V_ + v0n + chB * 8);
            }
        }

#pragma unroll
        for (int k16 = 0; k16 < 4; k16++) {
            const int colElem = k16 * 16 + laneColH * 8;
            uint32_t fa[4][4], fl[4][4], b[2][2];
#pragma unroll
            for (int mt = 0; mt < 4; mt++) {
                uint32_t adh = ahBase + ((mt * 16 + laneRow) * 72 + colElem) * 2;
                uint32_t adl = alBase + ((mt * 16 + laneRow) * 72 + colElem) * 2;
                ldsm_x4(fa[mt][0], fa[mt][1], fa[mt][2], fa[mt][3], adh);
                ldsm_x4(fl[mt][0], fl[mt][1], fl[mt][2], fl[mt][3], adl);
            }
            {
                uint32_t bd = bsBase + ((w * 16 + laneRow) * 72 + colElem) * 2;
                ldsm_x4(b[0][0], b[1][0], b[0][1], b[1][1], bd);
            }
#pragma unroll
            for (int mt = 0; mt < 4; mt++)
#pragma unroll
                for (int nt = 0; nt < 2; nt++) {
                    mma16816(acc[mt][nt], fa[mt], b[nt]);
                    mma16816(acc[mt][nt], fl[mt], b[nt]);
                }
        }
        __syncthreads();
    }
#pragma unroll
    for (int mt = 0; mt < 4; mt++) {
        int r = mt * 16 + g;
#pragma unroll
        for (int nt = 0; nt < 2; nt++) {
            int d = d0 + w * 16 + nt * 8 + 2 * t;
            uint32_t s0 = __float_as_uint(acc[mt][nt][0]);
            uint32_t s1 = __float_as_uint(acc[mt][nt][1]);
            uint32_t s2 = __float_as_uint(acc[mt][nt][2]);
            uint32_t s3 = __float_as_uint(acc[mt][nt][3]);
            uint32_t w0 = 0x3F803F80u | ((s0 >> 16) & 0x8000u) | (s1 & 0x80000000u);
            uint32_t w1 = 0x3F803F80u | ((s2 >> 16) & 0x8000u) | (s3 & 0x80000000u);
            ((uint32_t*)g_est_bf)[(((size_t)r * F_ + f) * D_ + d) >> 1] = w0;
            ((uint32_t*)g_est_bf)[(((size_t)(r + 8) * F_ + f) * D_ + d) >> 1] = w1;
        }
    }
}

// ---------------- outputs: est emit + outcome in ONE launch ----------------
#define EMIT_BLOCKS ((B_*F_*D_/2 + 255) / 256)     // 8192
__global__ void k_out(float* __restrict__ out, int do_outcome) {
    int blk = blockIdx.x;
    if (blk < EMIT_BLOCKS) {
        int i = blk * 256 + threadIdx.x;
        if (i < B_ * F_ * D_ / 2) {
            uint32_t w = ((const uint32_t*)g_est_bf)[i];
            float2 o;
            o.x = (w & 0x8000u) ? -1.f : 1.f;
            o.y = (w & 0x80000000u) ? -1.f : 1.f;
            ((float2*)out)[i] = o;
        }
    } else if (do_outcome) {
        int warp = (blk - EMIT_BLOCKS) * 8 + (threadIdx.x >> 5);
        int lane = threadIdx.x & 31;
        if (warp >= B_ * F_) return;
        int b = warp >> 2, f = warp & 3;
        const float* s = g_sim + ((size_t)(f * B_ + b)) * V_;
        float best = -1.f; int bi = 0;
#pragma unroll
        for (int j = 0; j < 8; j++) {
            int v = j * 32 + lane;
            float a = fabsf(s[v]);
            if (a > best) { best = a; bi = v; }
        }
#pragma unroll
        for (int off = 16; off; off >>= 1) {
            float ob = __shfl_down_sync(0xffffffffu, best, off);
            int   oi = __shfl_down_sync(0xffffffffu, bi, off);
            if (ob > best || (ob == best && oi < bi)) { best = ob; bi = oi; }
        }
        if (lane == 0) out[(size_t)B_ * F_ * D_ + warp] = (float)bi;
    }
}

// ---------------- host launch ----------------
extern "C" void kernel_launch(void* const* d_in, const int* in_sizes, int n_in,
                              void* d_out, int out_size) {
    const float *input = nullptr, *est0 = nullptr, *cb = nullptr;
    for (int i = 0; i < n_in; i++) {
        if      (in_sizes[i] == B_ * D_)        input = (const float*)d_in[i];
        else if (in_sizes[i] == B_ * F_ * D_)   est0  = (const float*)d_in[i];
        else if (in_sizes[i] == F_ * V_ * D_)   cb    = (const float*)d_in[i];
    }
    if (!input && n_in > 0) input = (const float*)d_in[0];
    if (!est0  && n_in > 1) est0  = (const float*)d_in[1];
    if (!cb    && n_in > 2) cb    = (const float*)d_in[2];

    k_signs<<<(NPAIRS_IN + NPAIRS_EST + 255) / 256, 256>>>(input, est0);
    k_cb<<<dim3(D_ / 32, V_ / 32, F_), 256>>>(cb);

    for (int it = 0; it < ITERS_; it++) {
        k_sim<<<dim3(KCH, F_), 256>>>(0);
        k_reduce<<<(F_ * B_ * V_) / 256, 256>>>();
        k_update<<<dim3(D_ / 128, F_), 256>>>();
    }
    // final similarity on converged estimates
    k_sim<<<dim3(KCH, F_), 256>>>(1);
    k_reduce<<<(F_ * B_ * V_) / 256, 256>>>();

    float* out = (float*)d_out;
    int do_outcome = (out_size >= B_ * F_ * D_ + B_ * F_) ? 1 : 0;
    int nblk = EMIT_BLOCKS + (do_outcome ? 32 : 0);
    k_out<<<nblk, 256>>>(out, do_outcome);
}

// round 11
// speedup vs baseline: 1.2957x; 1.0047x over previous
#include <cuda_runtime.h>
#include <cuda_bf16.h>
#include <stdint.h>

#define B_ 64
#define F_ 4
#define V_ 256
#define D_ 16384
#define ITERS_ 10
#define KCH 32               // split-K chunks for stage 2
#define KC (D_/KCH)          // 512 k per chunk

// ---------------- static device scratch (no runtime allocation) ----------------
__device__ __align__(16) __nv_bfloat16 g_in_bf [B_*D_];                 // input, +-1 bf16
__device__ __align__(16) __nv_bfloat16 g_est_bf[B_*F_*D_];              // current estimates, +-1 bf16
__device__ __align__(16) __nv_bfloat16 g_cbK   [(size_t)F_*V_*D_];      // codebook [f][v][d] bf16
__device__ __align__(16) __nv_bfloat16 g_cbD   [(size_t)F_*D_*V_];      // codebook [f][d][v] bf16
__device__ __align__(16) float         g_simp  [(size_t)KCH*F_*B_*V_];  // split-K partials
__device__ __align__(16) float         g_sim   [F_*B_*V_];              // reduced sim (exact ints)
__device__ __align__(16) __nv_bfloat16 g_Ah    [F_*B_*V_];              // sim & ~127 (exact bf16)
__device__ __align__(16) __nv_bfloat16 g_Al    [F_*B_*V_];              // sim &  127 (exact bf16)

// ---------------- mma.sync helper (bf16, fp32 accum — exact for our integer data) ----
__device__ __forceinline__ void mma16816(float c[4], const uint32_t a[4], const uint32_t b[2]) {
    asm volatile(
        "mma.sync.aligned.m16n8k16.row.col.f32.bf16.bf16.f32 "
        "{%0,%1,%2,%3},{%4,%5,%6,%7},{%8,%9},{%0,%1,%2,%3};\n"
        : "+f"(c[0]), "+f"(c[1]), "+f"(c[2]), "+f"(c[3])
        : "r"(a[0]), "r"(a[1]), "r"(a[2]), "r"(a[3]), "r"(b[0]), "r"(b[1]));
}

__device__ __forceinline__ void ldsm_x4(uint32_t& r0, uint32_t& r1, uint32_t& r2, uint32_t& r3,
                                        uint32_t saddr) {
    asm volatile("ldmatrix.sync.aligned.m8n8.x4.shared.b16 {%0,%1,%2,%3}, [%4];"
                 : "=r"(r0), "=r"(r1), "=r"(r2), "=r"(r3) : "r"(saddr));
}

// ---------------- setup: input + est signs in ONE launch ----------------
#define NPAIRS_IN  (B_*D_/2)        // 524288
#define NPAIRS_EST (B_*F_*D_/2)     // 2097152
__global__ void k_signs(const float* __restrict__ input, const float* __restrict__ est0) {
    int i = blockIdx.x * blockDim.x + threadIdx.x;
    if (i < NPAIRS_IN) {
        uint2 u = ((const uint2*)input)[i];
        ((uint32_t*)g_in_bf)[i] = 0x3F803F80u | ((u.x >> 16) & 0x8000u) | (u.y & 0x80000000u);
    } else {
        int j = i - NPAIRS_IN;
        if (j < NPAIRS_EST) {
            uint2 u = ((const uint2*)est0)[j];
            ((uint32_t*)g_est_bf)[j] = 0x3F803F80u | ((u.x >> 16) & 0x8000u) | (u.y & 0x80000000u);
        }
    }
}

// ---------------- setup: codebook -> cbK AND cbD from a single fp32 read -------------
__global__ void k_cb(const float* __restrict__ cb) {
    __shared__ unsigned short ts[32][33];
    int f = blockIdx.z, d0 = blockIdx.x * 32, v0 = blockIdx.y * 32;
    int tx = threadIdx.x & 31, ty = threadIdx.x >> 5;  // 32 x 8
#pragma unroll
    for (int r = 0; r < 4; r++) {
        int v = v0 + ty + r * 8;
        uint32_t ub = __float_as_uint(cb[((size_t)(f * V_ + v)) * D_ + d0 + tx]);
        unsigned short s = (unsigned short)(0x3F80u | ((ub >> 16) & 0x8000u));
        ts[ty + r * 8][tx] = s;
        ((unsigned short*)g_cbK)[((size_t)(f * V_ + v)) * D_ + d0 + tx] = s;   // row-major
    }
    __syncthreads();
#pragma unroll
    for (int r = 0; r < 4; r++) {
        int d = d0 + ty + r * 8;
        ((unsigned short*)g_cbD)[((size_t)(f * D_ + d)) * V_ + v0 + tx] = ts[tx][ty + r * 8];
    }
}

// ---------------- stage 2: sim[f][b][v] = sum_d n * cb -------------------------------
// 512 threads / block (16 warps): each warp handles a 64(M) x 16(N) tile.
// mode 0: n = input * prod(est) * est_f inline (6-word XOR); mode 1: n = est_f.
__global__ void __launch_bounds__(512) k_sim(int mode) {
    __shared__ __align__(16) __nv_bfloat16 As[64 * 72];
    __shared__ __align__(16) __nv_bfloat16 Bs[256 * 72];
    const int kc = blockIdx.x, f = blockIdx.y;
    const int tid = threadIdx.x;
    const int w = tid >> 5, lane = tid & 31, g = lane >> 2, t = lane & 3;
    const int arow = tid >> 3, aseg = tid & 7;       // A: 64 rows x 8 uint4 segments
    const int vB = tid >> 3, chB = tid & 7;          // B: 64 rows/pass x 8 segments

    const uint4* pin = (const uint4*)(g_in_bf + (size_t)arow * D_);
    const uint4* pef = (const uint4*)(g_est_bf + ((size_t)arow * F_ + f) * D_);

    const uint32_t asBase = (uint32_t)__cvta_generic_to_shared(As);
    const uint32_t bsBase = (uint32_t)__cvta_generic_to_shared(Bs);
    const int laneRow  = lane & 15;
    const int laneColH = (lane >> 4) & 1;

    float acc[4][2][4];
#pragma unroll
    for (int mt = 0; mt < 4; mt++)
#pragma unroll
        for (int nt = 0; nt < 2; nt++)
#pragma unroll
            for (int j = 0; j < 4; j++) acc[mt][nt][j] = 0.f;

    uint4 a0;                                  // final A word (prefetched+computed)
    uint4 rB[4];                               // B prefetch regs

    // ---- A prefetch/compute for a given k-offset (one uint4 per thread) ----
    auto prefetchA = [&](int k0, uint4& o0) {
        int ai = (k0 >> 3) + aseg;             // uint4 index (8 bf16 each)
        if (mode == 0) {
            uint4 x0 = pin[ai];
            uint4 f0 = make_uint4(0, 0, 0, 0);
#pragma unroll
            for (int ff = 0; ff < F_; ff++) {
                const uint4* pe = (const uint4*)(g_est_bf + ((size_t)arow * F_ + ff) * D_);
                uint4 e0 = pe[ai];
                x0.x ^= e0.x; x0.y ^= e0.y; x0.z ^= e0.z; x0.w ^= e0.w;
                if (ff == f) f0 = e0;
            }
            // est_f appears twice (total product and unbound factor) -> xor again
            x0.x ^= f0.x; x0.y ^= f0.y; x0.z ^= f0.z; x0.w ^= f0.w;
            // 6 valid +-1 bf16 words XORed -> magnitude bits cancel; restore
            o0.x = 0x3F803F80u ^ x0.x; o0.y = 0x3F803F80u ^ x0.y;
            o0.z = 0x3F803F80u ^ x0.z; o0.w = 0x3F803F80u ^ x0.w;
        } else {
            o0 = pef[ai];
        }
    };

    // preload ks=0
    {
        const int k0 = kc * KC;
        prefetchA(k0, a0);
#pragma unroll
        for (int p = 0; p < 4; p++) {
            int v = p * 64 + vB;
            rB[p] = *(const uint4*)(g_cbK + ((size_t)(f * V_ + v)) * D_ + k0 + chB * 8);
        }
    }

    for (int ks = 0; ks < KC / 64; ks++) {
        // ---- store current tile from regs ----
        {
            *(uint4*)((uint32_t*)As + arow * 36 + aseg * 4) = a0;
#pragma unroll
            for (int p = 0; p < 4; p++)
                *(uint4*)((uint32_t*)Bs + (p * 64 + vB) * 36 + chB * 4) = rB[p];
        }
        __syncthreads();

        // ---- prefetch next tile (overlapped with mma below) ----
        if (ks + 1 < KC / 64) {
            const int k0n = kc * KC + (ks + 1) * 64;
            prefetchA(k0n, a0);
#pragma unroll
            for (int p = 0; p < 4; p++) {
                int v = p * 64 + vB;
                rB[p] = *(const uint4*)(g_cbK + ((size_t)(f * V_ + v)) * D_ + k0n + chB * 8);
            }
        }

        // ---- mma over 4 k16 steps (ldmatrix fragments; proven patterns) ----
#pragma unroll
        for (int k16 = 0; k16 < 4; k16++) {
            const int colElem = k16 * 16 + laneColH * 8;
            uint32_t a[4][4], b[2][2];
#pragma unroll
            for (int mt = 0; mt < 4; mt++) {
                uint32_t ad = asBase + ((mt * 16 + laneRow) * 72 + colElem) * 2;
                ldsm_x4(a[mt][0], a[mt][1], a[mt][2], a[mt][3], ad);
            }
            {
                uint32_t bd = bsBase + ((w * 16 + laneRow) * 72 + colElem) * 2;
                ldsm_x4(b[0][0], b[1][0], b[0][1], b[1][1], bd);
            }
#pragma unroll
            for (int mt = 0; mt < 4; mt++)
#pragma unroll
                for (int nt = 0; nt < 2; nt++) mma16816(acc[mt][nt], a[mt], b[nt]);
        }
        __syncthreads();
    }
    // --- write split-K partials ---
    float* op = g_simp + ((size_t)(kc * F_ + f) * B_) * V_;
#pragma unroll
    for (int mt = 0; mt < 4; mt++) {
        int r = mt * 16 + g;
#pragma unroll
        for (int nt = 0; nt < 2; nt++) {
            int c = w * 16 + nt * 8 + 2 * t;
            *(float2*)&op[(size_t)r * V_ + c]       = make_float2(acc[mt][nt][0], acc[mt][nt][1]);
            *(float2*)&op[(size_t)(r + 8) * V_ + c] = make_float2(acc[mt][nt][2], acc[mt][nt][3]);
        }
    }
}

// ---------------- reduce partials: 2 threads/element + shfl (2x memory parallelism) ----
__global__ void k_reduce() {
    int gid = blockIdx.x * blockDim.x + threadIdx.x;    // 131072 threads
    int i = gid >> 1;                                   // element 0..65535
    int half = gid & 1;
    float s = 0.f;
#pragma unroll
    for (int j = 0; j < KCH / 2; j++)
        s += g_simp[(size_t)(half * (KCH / 2) + j) * (F_ * B_ * V_) + i];
    s += __shfl_xor_sync(0xffffffffu, s, 1);            // pair lanes 2k / 2k+1
    if (half == 0) {
        g_sim[i] = s;
        int si = (int)s;                                // exact integer
        g_Ah[i] = __float2bfloat16((float)(si & ~127)); // multiple of 128 -> exact bf16
        g_Al[i] = __float2bfloat16((float)(si & 127));  // 0..127 -> exact bf16
    }
}

// ---------------- stage 3: est = sign( sum_v sim * cbD ) ----------------
__global__ void __launch_bounds__(256) k_update() {
    __shared__ __align__(16) __nv_bfloat16 Bs[128 * 72];
    __shared__ __align__(16) __nv_bfloat16 Ahs[64 * 72];
    __shared__ __align__(16) __nv_bfloat16 Als[64 * 72];
    const int dt = blockIdx.x, f = blockIdx.y;
    const int d0 = dt * 128;
    const int tid = threadIdx.x;
    const int w = tid >> 5, lane = tid & 31, g = lane >> 2, t = lane & 3;
    const int arow = tid >> 2, aseg = tid & 3;
    const int dB = tid >> 3, chB = tid & 7;

    const uint32_t ahBase = (uint32_t)__cvta_generic_to_shared(Ahs);
    const uint32_t alBase = (uint32_t)__cvta_generic_to_shared(Als);
    const uint32_t bsBase = (uint32_t)__cvta_generic_to_shared(Bs);
    const int laneRow  = lane & 15;
    const int laneColH = (lane >> 4) & 1;

    float acc[4][2][4];
#pragma unroll
    for (int mt = 0; mt < 4; mt++)
#pragma unroll
        for (int nt = 0; nt < 2; nt++)
#pragma unroll
            for (int j = 0; j < 4; j++) acc[mt][nt][j] = 0.f;

    uint4 h0, h1, l0, l1;
    uint4 rB[4];
    {
        const int vv = aseg * 16;
        h0 = *(const uint4*)(g_Ah + ((size_t)f * B_ + arow) * V_ + vv);
        h1 = *(const uint4*)(g_Ah + ((size_t)f * B_ + arow) * V_ + vv + 8);
        l0 = *(const uint4*)(g_Al + ((size_t)f * B_ + arow) * V_ + vv);
        l1 = *(const uint4*)(g_Al + ((size_t)f * B_ + arow) * V_ + vv + 8);
#pragma unroll
        for (int p = 0; p < 4; p++) {
            int dl = p * 32 + dB;
            rB[p] = *(const uint4*)(g_cbD + ((size_t)(f * D_ + d0 + dl)) * V_ + chB * 8);
        }
    }

    for (int vs = 0; vs < 4; vs++) {
        {
            uint4* ah = (uint4*)((uint32_t*)Ahs + arow * 36 + aseg * 8);
            uint4* al = (uint4*)((uint32_t*)Als + arow * 36 + aseg * 8);
            ah[0] = h0; ah[1] = h1;
            al[0] = l0; al[1] = l1;
#pragma unroll
            for (int p = 0; p < 4; p++)
                *(uint4*)((uint32_t*)Bs + (p * 32 + dB) * 36 + chB * 4) = rB[p];
        }
        __syncthreads();

        if (vs + 1 < 4) {
            const int v0n = (vs + 1) * 64;
            const int vv = v0n + aseg * 16;
            h0 = *(const uint4*)(g_Ah + ((size_t)f * B_ + arow) * V_ + vv);
            h1 = *(const uint4*)(g_Ah + ((size_t)f * B_ + arow) * V_ + vv + 8);
            l0 = *(const uint4*)(g_Al + ((size_t)f * B_ + arow) * V_ + vv);
            l1 = *(const uint4*)(g_Al + ((size_t)f * B_ + arow) * V_ + vv + 8);
#pragma unroll
            for (int p = 0; p < 4; p++) {
                int dl = p * 32 + dB;
                rB[p] = *(const uint4*)(g_cbD + ((size_t)(f * D_ + d0 + dl)) * V_ + v0n + chB * 8);
            }
        }

#pragma unroll
        for (int k16 = 0; k16 < 4; k16++) {
            const int colElem = k16 * 16 + laneColH * 8;
            uint32_t fa[4][4], fl[4][4], b[2][2];
#pragma unroll
            for (int mt = 0; mt < 4; mt++) {
                uint32_t adh = ahBase + ((mt * 16 + laneRow) * 72 + colElem) * 2;
                uint32_t adl = alBase + ((mt * 16 + laneRow) * 72 + colElem) * 2;
                ldsm_x4(fa[mt][0], fa[mt][1], fa[mt][2], fa[mt][3], adh);
                ldsm_x4(fl[mt][0], fl[mt][1], fl[mt][2], fl[mt][3], adl);
            }
            {
                uint32_t bd = bsBase + ((w * 16 + laneRow) * 72 + colElem) * 2;
                ldsm_x4(b[0][0], b[1][0], b[0][1], b[1][1], bd);
            }
#pragma unroll
            for (int mt = 0; mt < 4; mt++)
#pragma unroll
                for (int nt = 0; nt < 2; nt++) {
                    mma16816(acc[mt][nt], fa[mt], b[nt]);
                    mma16816(acc[mt][nt], fl[mt], b[nt]);
                }
        }
        __syncthreads();
    }
#pragma unroll
    for (int mt = 0; mt < 4; mt++) {
        int r = mt * 16 + g;
#pragma unroll
        for (int nt = 0; nt < 2; nt++) {
            int d = d0 + w * 16 + nt * 8 + 2 * t;
            uint32_t s0 = __float_as_uint(acc[mt][nt][0]);
            uint32_t s1 = __float_as_uint(acc[mt][nt][1]);
            uint32_t s2 = __float_as_uint(acc[mt][nt][2]);
            uint32_t s3 = __float_as_uint(acc[mt][nt][3]);
            uint32_t w0 = 0x3F803F80u | ((s0 >> 16) & 0x8000u) | (s1 & 0x80000000u);
            uint32_t w1 = 0x3F803F80u | ((s2 >> 16) & 0x8000u) | (s3 & 0x80000000u);
            ((uint32_t*)g_est_bf)[(((size_t)r * F_ + f) * D_ + d) >> 1] = w0;
            ((uint32_t*)g_est_bf)[(((size_t)(r + 8) * F_ + f) * D_ + d) >> 1] = w1;
        }
    }
}

// ---------------- outputs: est emit + outcome in ONE launch ----------------
#define EMIT_BLOCKS ((B_*F_*D_/2 + 255) / 256)     // 8192
__global__ void k_out(float* __restrict__ out, int do_outcome) {
    int blk = blockIdx.x;
    if (blk < EMIT_BLOCKS) {
        int i = blk * 256 + threadIdx.x;
        if (i < B_ * F_ * D_ / 2) {
            uint32_t w = ((const uint32_t*)g_est_bf)[i];
            float2 o;
            o.x = (w & 0x8000u) ? -1.f : 1.f;
            o.y = (w & 0x80000000u) ? -1.f : 1.f;
            ((float2*)out)[i] = o;
        }
    } else if (do_outcome) {
        int warp = (blk - EMIT_BLOCKS) * 8 + (threadIdx.x >> 5);
        int lane = threadIdx.x & 31;
        if (warp >= B_ * F_) return;
        int b = warp >> 2, f = warp & 3;
        const float* s = g_sim + ((size_t)(f * B_ + b)) * V_;
        float best = -1.f; int bi = 0;
#pragma unroll
        for (int j = 0; j < 8; j++) {
            int v = j * 32 + lane;
            float a = fabsf(s[v]);
            if (a > best) { best = a; bi = v; }
        }
#pragma unroll
        for (int off = 16; off; off >>= 1) {
            float ob = __shfl_down_sync(0xffffffffu, best, off);
            int   oi = __shfl_down_sync(0xffffffffu, bi, off);
            if (ob > best || (ob == best && oi < bi)) { best = ob; bi = oi; }
        }
        if (lane == 0) out[(size_t)B_ * F_ * D_ + warp] = (float)bi;
    }
}

// ---------------- host launch ----------------
extern "C" void kernel_launch(void* const* d_in, const int* in_sizes, int n_in,
                              void* d_out, int out_size) {
    const float *input = nullptr, *est0 = nullptr, *cb = nullptr;
    for (int i = 0; i < n_in; i++) {
        if      (in_sizes[i] == B_ * D_)        input = (const float*)d_in[i];
        else if (in_sizes[i] == B_ * F_ * D_)   est0  = (const float*)d_in[i];
        else if (in_sizes[i] == F_ * V_ * D_)   cb    = (const float*)d_in[i];
    }
    if (!input && n_in > 0) input = (const float*)d_in[0];
    if (!est0  && n_in > 1) est0  = (const float*)d_in[1];
    if (!cb    && n_in > 2) cb    = (const float*)d_in[2];

    k_signs<<<(NPAIRS_IN + NPAIRS_EST + 255) / 256, 256>>>(input, est0);
    k_cb<<<dim3(D_ / 32, V_ / 32, F_), 256>>>(cb);

    for (int it = 0; it < ITERS_; it++) {
        k_sim<<<dim3(KCH, F_), 512>>>(0);
        k_reduce<<<512, 256>>>();
        k_update<<<dim3(D_ / 128, F_), 256>>>();
    }
    // final similarity on converged estimates
    k_sim<<<dim3(KCH, F_), 512>>>(1);
    k_reduce<<<512, 256>>>();

    float* out = (float*)d_out;
    int do_outcome = (out_size >= B_ * F_ * D_ + B_ * F_) ? 1 : 0;
    int nblk = EMIT_BLOCKS + (do_outcome ? 32 : 0);
    k_out<<<nblk, 256>>>(out, do_outcome);
}